// round 8
// baseline (speedup 1.0000x reference)
#include <cuda_runtime.h>
#include <math.h>

// Problem shapes (fixed by the dataset)
#define HW_   (768 * 768)       // pixels
#define NQ_   (HW_ / 4)         // pixel float4 quads
#define S_    8192              // chamfer points per cloud
#define NG_   100000            // gradients / sdf
#define NEQ_  (NG_ / 4)         // eik quads
#define NP_   50000             // consistency points

// Fused-kernel geometry
#define NBLK  148               // one block per SM, single wave
#define NTH   512
#define C_CH  128               // chamfer blocks: 2 dirs x 64 dest-strides
#define NMEM  (NBLK - C_CH)     // 20 memory-task blocks
#define NSUB  64                // dest-stride blocks per direction
#define SPT   16                // sources per thread (whole cloud per block)
#define DCH   64                // dest tile size
#define NCHK  (S_ / DCH)        // 128 dest tiles (2 per chamfer block)

// Scratch (device globals; fully written every launch, no init needed)
__device__ float  g_minpart[2][NSUB][S_];     // per-(dir,stride) partial row mins
__device__ double g_part[NBLK][12];           // per-block term partials
__device__ unsigned long long g_sync[2];      // monotone sync counters (never reset)

// ---------------------------------------------------------------------------
// Reductions
// ---------------------------------------------------------------------------
__device__ __forceinline__ float warpSum(float v) {
    #pragma unroll
    for (int o = 16; o > 0; o >>= 1) v += __shfl_down_sync(0xffffffffu, v, o);
    return v;
}
__device__ float blockSum(float v) {
    __shared__ float s[32];
    int lane = threadIdx.x & 31, wid = threadIdx.x >> 5;
    __syncthreads();
    v = warpSum(v);
    if (lane == 0) s[wid] = v;
    __syncthreads();
    v = (threadIdx.x < (NTH / 32)) ? s[threadIdx.x] : 0.0f;
    if (wid == 0) v = warpSum(v);
    return v;
}
__device__ __forceinline__ double dwarpSum(double v) {
    #pragma unroll
    for (int o = 16; o > 0; o >>= 1) v += __shfl_down_sync(0xffffffffu, v, o);
    return v;
}
__device__ double dblockSum(double v) {
    __shared__ double sd[32];
    int lane = threadIdx.x & 31, wid = threadIdx.x >> 5;
    __syncthreads();
    v = dwarpSum(v);
    if (lane == 0) sd[wid] = v;
    __syncthreads();
    v = (threadIdx.x < (NTH / 32)) ? sd[threadIdx.x] : 0.0;
    if (wid == 0) v = dwarpSum(v);
    return v;
}

// ---------------------------------------------------------------------------
// Grid-wide sync. Counter is never reset; each launch adds exactly NBLK per
// counter, so "count % NBLK == 0" <=> all blocks of THIS launch arrived.
// ---------------------------------------------------------------------------
__device__ __forceinline__ void gridSync(int s) {
    __syncthreads();
    if (threadIdx.x == 0) {
        __threadfence();
        atomicAdd(&g_sync[s], 1ULL);
        while ((*(volatile unsigned long long*)&g_sync[s]) % NBLK != 0ULL)
            __nanosleep(64);
        __threadfence();
    }
    __syncthreads();
}

// ---------------------------------------------------------------------------
// The fused kernel
// ---------------------------------------------------------------------------
__global__ void __launch_bounds__(NTH, 1)
k_fused(const float* __restrict__ npred, const float* __restrict__ ngt,
        const float* __restrict__ dpred, const float* __restrict__ dgt,
        const float* __restrict__ X,     const float* __restrict__ Y,
        const float* __restrict__ mask,  const float* __restrict__ comp,
        const float* __restrict__ grad,  const float* __restrict__ sdf,
        const float* __restrict__ nw,    const float* __restrict__ vis,
        const float* __restrict__ w,     float* __restrict__ out) {
    const int bid = blockIdx.x;
    const int t   = threadIdx.x;

    // ======================= PHASE 1 =======================
    if (bid < C_CH) {
        // ---- chamfer role: scalar row-min, one direction per block-group ----
        __shared__ float ty0[DCH];   // -2*y0
        __shared__ float ty1[DCH];   // -2*y1
        __shared__ float ty2[DCH];   // -2*y2
        __shared__ float tyy[DCH];   // y.y

        const int dir = bid >> 6;              // 0: X->Y rows, 1: Y->X rows
        const int sub = bid & (NSUB - 1);      // dest-tile stride offset
        const float* src = dir ? Y : X;
        const float* dst = dir ? X : Y;

        // Load all 8192 sources: 16 per thread, strided by NTH
        float sx0[SPT], sx1[SPT], sx2[SPT], xx[SPT], best[SPT];
        #pragma unroll
        for (int k = 0; k < SPT; k++) {
            const int si = t + k * NTH;
            float a = __ldg(&src[3 * si + 0]);
            float b = __ldg(&src[3 * si + 1]);
            float c = __ldg(&src[3 * si + 2]);
            sx0[k] = a; sx1[k] = b; sx2[k] = c;
            xx[k]  = fmaf(a, a, fmaf(b, b, c * c));
            best[k] = 3.4e38f;
        }

        // Two dest tiles per block: chunks sub and sub+NSUB
        #pragma unroll
        for (int cc = 0; cc < NCHK / NSUB; cc++) {
            const int chunk = sub + cc * NSUB;
            __syncthreads();                   // smem free (prev tile done)
            if (t < DCH) {
                const int p = chunk * DCH + t;
                float y0 = dst[3 * p + 0];
                float y1 = dst[3 * p + 1];
                float y2 = dst[3 * p + 2];
                ty0[t] = -2.0f * y0;
                ty1[t] = -2.0f * y1;
                ty2[t] = -2.0f * y2;
                tyy[t] = fmaf(y0, y0, fmaf(y1, y1, y2 * y2));
            }
            __syncthreads();

            // Prefetch j=0 values, iterate with one-ahead register prefetch
            float na = ty0[0], nb = ty1[0], nc = ty2[0], nv = tyy[0];
            #pragma unroll 2
            for (int j = 0; j < DCH; j++) {
                const float a = na, b = nb, c = nc, v = nv;
                if (j + 1 < DCH) {
                    na = ty0[j + 1]; nb = ty1[j + 1];
                    nc = ty2[j + 1]; nv = tyy[j + 1];
                }
                #pragma unroll
                for (int k = 0; k < SPT; k++) {
                    float d = fmaf(sx0[k], a, v);
                    d = fmaf(sx1[k], b, d);
                    d = fmaf(sx2[k], c, d);
                    best[k] = fminf(best[k], d);
                }
            }
        }
        // Write partial row mins (full d^2 = xx + (yy - 2 x.y))
        #pragma unroll
        for (int k = 0; k < SPT; k++)
            g_minpart[dir][sub][t + k * NTH] = xx[k] + best[k];
    } else {
        // ---------------- memory role ----------------
        const int mb   = bid - C_CH;
        const int gtid = mb * NTH + t;
        const int MT   = NMEM * NTH;

        // pixel reductions
        float cnt = 0.f, nerr = 0.f, den = 0.f, num = 0.f, bce = 0.f;
        const float4* m4p = (const float4*)mask;
        const float4* c4p = (const float4*)comp;
        const float4* g4p = (const float4*)dgt;
        const float4* p4p = (const float4*)dpred;
        const float4* np4 = (const float4*)npred;
        const float4* ng4 = (const float4*)ngt;
        for (int q = gtid; q < NQ_; q += MT) {
            float4 m4 = m4p[q], c4 = c4p[q], g4 = g4p[q], p4 = p4p[q];
            float4 a0 = np4[3 * q + 0], a1 = np4[3 * q + 1], a2 = np4[3 * q + 2];
            float4 b0 = ng4[3 * q + 0], b1 = ng4[3 * q + 1], b2 = ng4[3 * q + 2];
            float m[4] = { m4.x > 0.5f ? 1.f : 0.f, m4.y > 0.5f ? 1.f : 0.f,
                           m4.z > 0.5f ? 1.f : 0.f, m4.w > 0.5f ? 1.f : 0.f };
            float cc[4] = { c4.x, c4.y, c4.z, c4.w };
            float gg[4] = { g4.x, g4.y, g4.z, g4.w };
            float pp[4] = { p4.x, p4.y, p4.z, p4.w };
            float e[4];
            { float d0=a0.x-b0.x, d1=a0.y-b0.y, d2=a0.z-b0.z; e[0]=fmaf(d0,d0,fmaf(d1,d1,d2*d2)); }
            { float d0=a0.w-b0.w, d1=a1.x-b1.x, d2=a1.y-b1.y; e[1]=fmaf(d0,d0,fmaf(d1,d1,d2*d2)); }
            { float d0=a1.z-b1.z, d1=a1.w-b1.w, d2=a2.x-b2.x; e[2]=fmaf(d0,d0,fmaf(d1,d1,d2*d2)); }
            { float d0=a2.y-b2.y, d1=a2.z-b2.z, d2=a2.w-b2.w; e[3]=fmaf(d0,d0,fmaf(d1,d1,d2*d2)); }
            #pragma unroll
            for (int k = 0; k < 4; k++) {
                cnt  += m[k];
                nerr += m[k] * e[k];
                float vg = m[k] * gg[k], vp = m[k] * pp[k];
                den = fmaf(vg, vg, den);
                num = fmaf(vg, vp, num);
                float c = fminf(fmaxf(cc[k], 1e-5f), 1.0f - 1e-5f);
                bce += m[k] * __logf(c) + (1.0f - m[k]) * __logf(1.0f - c);
            }
        }

        // eikonal + sdf
        float eik = 0.f, sda = 0.f;
        const float4* gr4 = (const float4*)grad;
        const float4* sd4 = (const float4*)sdf;
        for (int q = gtid; q < NEQ_; q += MT) {
            float4 g0 = gr4[3 * q + 0], g1 = gr4[3 * q + 1], g2 = gr4[3 * q + 2];
            float4 s4 = sd4[q];
            float n;
            n = sqrtf(fmaf(g0.x,g0.x,fmaf(g0.y,g0.y,g0.z*g0.z))) - 1.f; eik = fmaf(n,n,eik);
            n = sqrtf(fmaf(g0.w,g0.w,fmaf(g1.x,g1.x,g1.y*g1.y))) - 1.f; eik = fmaf(n,n,eik);
            n = sqrtf(fmaf(g1.z,g1.z,fmaf(g1.w,g1.w,g2.x*g2.x))) - 1.f; eik = fmaf(n,n,eik);
            n = sqrtf(fmaf(g2.y,g2.y,fmaf(g2.z,g2.z,g2.w*g2.w))) - 1.f; eik = fmaf(n,n,eik);
            sda += fabsf(s4.x) + fabsf(s4.y) + fabsf(s4.z) + fabsf(s4.w);
        }

        // consistency
        float con = 0.f, tot = 0.f;
        const float4* nw4  = (const float4*)nw;
        const float4* vs4  = (const float4*)vis;
        for (int p = gtid; p < NP_; p += MT) {
            float wt = w[p];
            float4 v  = vs4[p];
            float4 n0 = nw4[3 * p + 0], n1 = nw4[3 * p + 1], n2 = nw4[3 * p + 2];
            { float vp = v.x*v.y; tot += vp;
              float d0=n0.x-n0.w, d1=n0.y-n1.x, d2=n0.z-n1.y;
              con = fmaf(fmaf(d0,d0,fmaf(d1,d1,d2*d2))*vp, wt, con); }
            { float vp = v.y*v.z; tot += vp;
              float d0=n0.w-n1.z, d1=n1.x-n1.w, d2=n1.y-n2.x;
              con = fmaf(fmaf(d0,d0,fmaf(d1,d1,d2*d2))*vp, wt, con); }
            { float vp = v.z*v.w; tot += vp;
              float d0=n1.z-n2.y, d1=n1.w-n2.z, d2=n2.x-n2.w;
              con = fmaf(fmaf(d0,d0,fmaf(d1,d1,d2*d2))*vp, wt, con); }
        }

        float r;
        r = blockSum(cnt);  if (t == 0) g_part[bid][0] = (double)r;
        r = blockSum(nerr); if (t == 0) g_part[bid][1] = (double)r;
        r = blockSum(den);  if (t == 0) g_part[bid][2] = (double)r;
        r = blockSum(num);  if (t == 0) g_part[bid][3] = (double)r;
        r = blockSum(bce);  if (t == 0) g_part[bid][4] = (double)r;
        r = blockSum(eik);  if (t == 0) g_part[bid][5] = (double)r;
        r = blockSum(sda);  if (t == 0) g_part[bid][6] = (double)r;
        r = blockSum(con);  if (t == 0) g_part[bid][7] = (double)r;
        r = blockSum(tot);  if (t == 0) g_part[bid][8] = (double)r;
    }

    // ======================= SYNC A =======================
    gridSync(0);

    // ======================= PHASE 2 =======================
    // depth second pass (needs scale from phase-1 den/num partials)
    {
        double dden = 0.0, dnum = 0.0;
        #pragma unroll
        for (int i = 0; i < NMEM; i++) {
            dden += g_part[C_CH + i][2];
            dnum += g_part[C_CH + i][3];
        }
        float scale = (float)(dnum / dden);
        if (!isfinite(scale)) scale = 1.0f;

        float ds = 0.f;
        const float4* m4p = (const float4*)mask;
        const float4* g4p = (const float4*)dgt;
        const float4* p4p = (const float4*)dpred;
        for (int q = bid * NTH + t; q < NQ_; q += NBLK * NTH) {
            float4 m4 = m4p[q], g4 = g4p[q], p4 = p4p[q];
            float m;
            m = m4.x > 0.5f ? 1.f : 0.f; ds += fabsf(fmaf(m*g4.x, scale, -(m*p4.x)));
            m = m4.y > 0.5f ? 1.f : 0.f; ds += fabsf(fmaf(m*g4.y, scale, -(m*p4.y)));
            m = m4.z > 0.5f ? 1.f : 0.f; ds += fabsf(fmaf(m*g4.z, scale, -(m*p4.z)));
            m = m4.w > 0.5f ? 1.f : 0.f; ds += fabsf(fmaf(m*g4.w, scale, -(m*p4.w)));
        }
        float r = blockSum(ds);
        if (t == 0) g_part[bid][9] = (double)r;
    }
    // chamfer: reduce row-min partials over the 64 dest-strides, then sqrt
    {
        float ss = 0.f;
        for (int s = bid * NTH + t; s < 2 * S_; s += NBLK * NTH) {
            const int dir = s >> 13;            // / S_ (8192)
            const int idx = s & (S_ - 1);
            float mn = 3.4e38f;
            #pragma unroll 8
            for (int sub = 0; sub < NSUB; sub++)
                mn = fminf(mn, g_minpart[dir][sub][idx]);
            ss += sqrtf(fmaxf(mn, 0.0f));
        }
        float r = blockSum(ss);
        if (t == 0) g_part[bid][10] = (double)r;
    }

    // ======================= SYNC B =======================
    gridSync(1);

    // ======================= FINAL (block 0) =======================
    if (bid == 0) {
        double sum[11];
        #pragma unroll
        for (int term = 0; term < 9; term++) {
            double v = (t < NMEM) ? g_part[C_CH + t][term] : 0.0;
            sum[term] = dblockSum(v);
        }
        { double v = (t < NBLK) ? g_part[t][9]  : 0.0; sum[9]  = dblockSum(v); }
        { double v = (t < NBLK) ? g_part[t][10] : 0.0; sum[10] = dblockSum(v); }

        if (t == 0) {
            double mask_sum = sum[0] + 1e-5;
            double normal_loss = sum[1] / mask_sum;

            double den = sum[2];
            double depth_loss = sum[9] / (mask_sum + 1e-8);
            if (den < 1e-10) depth_loss = 0.0;
            if (!isfinite(depth_loss)) depth_loss = 0.0;

            double pc_loss   = sum[10] / (double)S_;
            double mask_loss = -sum[4] / (double)HW_;
            double eik_loss  = sum[5] / (double)NG_;
            double sdf_loss  = sum[6] / (double)NG_;
            double con_loss  = (sum[8] > 0.0) ? (sum[7] / sum[8]) : 0.0;

            out[0] = (float)(normal_loss + depth_loss + pc_loss + mask_loss +
                             eik_loss + sdf_loss + con_loss);
        }
    }
}

// ---------------------------------------------------------------------------
// Launch
// ---------------------------------------------------------------------------
extern "C" void kernel_launch(void* const* d_in, const int* in_sizes, int n_in,
                              void* d_out, int out_size) {
    const float* normal_pred = (const float*)d_in[0];
    const float* normal_gt   = (const float*)d_in[1];
    const float* depth_pred  = (const float*)d_in[2];
    const float* depth_gt    = (const float*)d_in[3];
    const float* X           = (const float*)d_in[4];
    const float* Y           = (const float*)d_in[5];
    const float* mask        = (const float*)d_in[6];
    const float* comp_mask   = (const float*)d_in[7];
    const float* gradients   = (const float*)d_in[8];
    const float* sdf         = (const float*)d_in[9];
    const float* nw_all      = (const float*)d_in[10];
    const float* vis_mask    = (const float*)d_in[11];
    const float* weights     = (const float*)d_in[12];
    float* out = (float*)d_out;

    k_fused<<<NBLK, NTH>>>(normal_pred, normal_gt, depth_pred, depth_gt,
                           X, Y, mask, comp_mask, gradients, sdf,
                           nw_all, vis_mask, weights, out);
}